// round 15
// baseline (speedup 1.0000x reference)
#include <cuda_runtime.h>
#include <cuda_bf16.h>
#include <cuda_fp16.h>
#include <math.h>
#include <cstdint>

// Problem constants
#define BATCH   8
#define CH      256
#define HH      128
#define WW_     128
#define HWTOK   (HH*WW_)            // 16384
#define MTOK    (BATCH*HWTOK)       // 131072
#define HID     1024
#define NHEAD   8
#define HDIM    32
#define WSZ     8
#define WTOK    (WSZ*WSZ)           // 64
#define NWIN    (MTOK/WTOK)         // 2048
#define QKV_STR 768
#define PGRID   296                 // 2 CTAs x 148 SMs, persistent

#if defined(__CUDA_ARCH__) && (defined(__CUDA_ARCH_FEAT_SM103_ALL) || \
    (defined(__CUDA_ARCH_SPECIFIC__)) || (defined(__CUDA_ARCH_FAMILY_SPECIFIC__)))
#define HAS_TCGEN05 1
#else
#define HAS_TCGEN05 0
#endif

// ===================== PTX helpers (inlined, sm_103a) =====================
__device__ __forceinline__ uint32_t elect_one_pred() {
    uint32_t pred;
    asm volatile("{\n\t.reg .pred p;\n\telect.sync _|p, 0xFFFFFFFF;\n\t"
                 "selp.b32 %0, 1, 0, p;\n\t}" : "=r"(pred));
    return pred;
}
__device__ __forceinline__ uint32_t smem_to_u32(const void* p) {
    uint32_t a;
    asm("{ .reg .u64 t; cvta.to.shared.u64 t, %1; cvt.u32.u64 %0, t; }" : "=r"(a) : "l"(p));
    return a;
}
static constexpr uint64_t SMEM_DESC_BASE_SW128 =
    (uint64_t(2) << 61) | (uint64_t(1) << 46) | (uint64_t(64) << 32) | (uint64_t(1) << 16);
#define MAKE_SMEM_DESC(base_addr) \
    (SMEM_DESC_BASE_SW128 | ((uint64_t)((base_addr) >> 4) & 0x3FFF))
#define SMEM_SWIZZLE_128B(off) ((off) ^ (((off) >> 3) & 0x70))

#if HAS_TCGEN05
#define TCGEN05_ALLOC(smem_result_addr, nCols) \
    asm volatile("tcgen05.alloc.cta_group::1.sync.aligned.shared::cta.b32 [%0], %1;" \
        :: "r"((uint32_t)(smem_result_addr)), "r"((uint32_t)(nCols)) : "memory")
#define TCGEN05_DEALLOC(tmem_addr, nCols) \
    asm volatile("tcgen05.dealloc.cta_group::1.sync.aligned.b32 %0, %1;" \
        :: "r"(tmem_addr), "r"((uint32_t)(nCols)))
#define TCGEN05_RELINQUISH() \
    asm volatile("tcgen05.relinquish_alloc_permit.cta_group::1.sync.aligned;")
#define TCGEN05_COMMIT(mbar) \
    asm volatile("tcgen05.commit.cta_group::1.mbarrier::arrive::one.shared::cluster.b64 [%0];" \
        :: "r"((uint32_t)(mbar)) : "memory")
#define TCGEN05_FENCE_AFTER() \
    asm volatile("tcgen05.fence::after_thread_sync;" ::: "memory")
#define TCGEN05_FENCE_BEFORE() \
    asm volatile("tcgen05.fence::before_thread_sync;" ::: "memory")
#define TCGEN05_WAIT_LD() \
    asm volatile("tcgen05.wait::ld.sync.aligned;" ::: "memory")
#define TCGEN05_LD_X32(r, addr) \
    asm volatile("tcgen05.ld.sync.aligned.32x32b.x32.b32 " \
        "{%0, %1, %2, %3, %4, %5, %6, %7, %8, %9, %10, %11, %12, %13, %14, %15, " \
        " %16, %17, %18, %19, %20, %21, %22, %23, %24, %25, %26, %27, %28, %29, %30, %31}, [%32];" \
        : "=r"((r)[0]),  "=r"((r)[1]),  "=r"((r)[2]),  "=r"((r)[3]), \
          "=r"((r)[4]),  "=r"((r)[5]),  "=r"((r)[6]),  "=r"((r)[7]), \
          "=r"((r)[8]),  "=r"((r)[9]),  "=r"((r)[10]), "=r"((r)[11]), \
          "=r"((r)[12]), "=r"((r)[13]), "=r"((r)[14]), "=r"((r)[15]), \
          "=r"((r)[16]), "=r"((r)[17]), "=r"((r)[18]), "=r"((r)[19]), \
          "=r"((r)[20]), "=r"((r)[21]), "=r"((r)[22]), "=r"((r)[23]), \
          "=r"((r)[24]), "=r"((r)[25]), "=r"((r)[26]), "=r"((r)[27]), \
          "=r"((r)[28]), "=r"((r)[29]), "=r"((r)[30]), "=r"((r)[31]) \
        : "r"(addr))
__device__ __forceinline__ void mma_f16_ss(uint32_t d, uint64_t a, uint64_t b,
                                           uint32_t idesc, uint32_t acc) {
    asm volatile(
        "{\n\t.reg .pred p;\n\tsetp.ne.u32 p, %4, 0;\n\t"
        "tcgen05.mma.cta_group::1.kind::f16 [%0], %1, %2, %3, {%5, %5, %5, %5}, p;\n\t}"
        :: "r"(d), "l"(a), "l"(b), "r"(idesc), "r"(acc), "r"(0u) : "memory");
}
// packed f32x2 FMA
__device__ __forceinline__ uint64_t pack2(float x, float y) {
    uint64_t r; asm("mov.b64 %0, {%1, %2};" : "=l"(r) : "f"(x), "f"(y)); return r;
}
__device__ __forceinline__ void unpack2(uint64_t v, float& x, float& y) {
    asm("mov.b64 {%0, %1}, %2;" : "=f"(x), "=f"(y) : "l"(v));
}
__device__ __forceinline__ uint64_t fma2(uint64_t a, uint64_t b, uint64_t c) {
    uint64_t d; asm("fma.rn.f32x2 %0, %1, %2, %3;" : "=l"(d) : "l"(a), "l"(b), "l"(c));
    return d;
}
#endif // HAS_TCGEN05

#define FENCE_PROXY_ASYNC() \
    asm volatile("fence.proxy.async.shared::cta;" ::: "memory")
#define MBARRIER_INIT(mbar, cnt) \
    asm volatile("mbarrier.init.shared.b64 [%0], %1;" \
        :: "r"((uint32_t)(mbar)), "r"((uint32_t)(cnt)) : "memory")
#define MBARRIER_WAIT_PARITY(mbar, parity) do { \
    uint32_t _m = (uint32_t)(mbar); uint32_t _p = (uint32_t)(parity); uint32_t _d; \
    asm volatile("{\n\t.reg .pred p;\n\t" \
        "mbarrier.try_wait.parity.acquire.cta.shared::cta.b64 p, [%1], %2;\n\t" \
        "selp.b32 %0, 1, 0, p;\n\t}" : "=r"(_d) : "r"(_m), "r"(_p) : "memory"); \
    if (!_d) { \
        asm volatile("{\n\t.reg .pred P1;\n\t" \
            "WL_%=:\n\t" \
            "mbarrier.try_wait.parity.acquire.cta.shared::cta.b64 P1, [%0], %1, 0x989680;\n\t" \
            "@P1 bra.uni WD_%=;\n\t" \
            "bra.uni WL_%=;\n\t" \
            "WD_%=:\n\t}" :: "r"(_m), "r"(_p) : "memory"); \
    } \
} while(0)

// idesc: dtype=F32, atype=FP16(0), btype=FP16(0), N=128 (16<<17), M=128 (8<<24)
#define GEMM_IDESC ((1u<<4)|(16u<<17)|(8u<<24))

// ===================== scratch (static device globals) =====================
__device__ float g_qkv  [(size_t)MTOK*QKV_STR];
__device__ float g_unary[(size_t)MTOK*CH];
__device__ float g_x2   [(size_t)MTOK*CH];
__device__ float g_bqkv [QKV_STR];
__device__ __align__(16) __half g_xh [(size_t)MTOK*CH];
__device__ __align__(16) __half g_th [(size_t)MTOK*CH];
__device__ __align__(16) __half g_nh [(size_t)MTOK*CH];
__device__ __align__(16) __half g_oh [(size_t)MTOK*CH];
__device__ __align__(16) __half g_lh [(size_t)MTOK*CH];
__device__ __align__(16) __half g_hh [(size_t)MTOK*HID];
#define WOFF_Q   0
#define WOFF_K   65536
#define WOFF_V   131072
#define WOFF_O   196608
#define WOFF_U1  262144
#define WOFF_U2  327680
#define WOFF_M1  393216
#define WOFF_M2  655360
__device__ __align__(16) __half g_wthi[917504];
__device__ __align__(16) __half g_wtlo[917504];

__device__ __forceinline__ float gelu_f(float x) {
    return 0.5f * x * (1.0f + erff(x * 0.70710678118654752f));
}
__device__ __forceinline__ void split_h(float v, __half& h, __half& l) {
    h = __float2half_rn(v);
    l = __float2half_rn(v - __half2float(h));
}

// ======= weight prep (all 8 weights, one launch): W(KxN) -> T(NxK) hi/lo ===
__global__ void wprep_all(const float* __restrict__ Wq, const float* __restrict__ Wk,
                          const float* __restrict__ Wv, const float* __restrict__ Wo,
                          const float* __restrict__ Wu1, const float* __restrict__ Wu2,
                          const float* __restrict__ Wm1, const float* __restrict__ Wm2,
                          __half* __restrict__ Thi, __half* __restrict__ Tlo) {
    const float* W; int K, N, off;
    switch (blockIdx.z) {
        case 0: W = Wq;  K = 256;  N = 256;  off = WOFF_Q;  break;
        case 1: W = Wk;  K = 256;  N = 256;  off = WOFF_K;  break;
        case 2: W = Wv;  K = 256;  N = 256;  off = WOFF_V;  break;
        case 3: W = Wo;  K = 256;  N = 256;  off = WOFF_O;  break;
        case 4: W = Wu1; K = 256;  N = 256;  off = WOFF_U1; break;
        case 5: W = Wu2; K = 256;  N = 256;  off = WOFF_U2; break;
        case 6: W = Wm1; K = 256;  N = 1024; off = WOFF_M1; break;
        default:W = Wm2; K = 1024; N = 256;  off = WOFF_M2; break;
    }
    const int n0 = blockIdx.x << 5, k0 = blockIdx.y << 5;
    if (n0 >= N || k0 >= K) return;
    __shared__ float t[32][33];
    const int x = threadIdx.x, y = threadIdx.y;
#pragma unroll
    for (int yy = 0; yy < 4; ++yy) {
        int kl = y + (yy << 3);
        t[kl][x] = W[(size_t)(k0 + kl) * N + n0 + x];
    }
    __syncthreads();
#pragma unroll
    for (int yy = 0; yy < 4; ++yy) {
        int nl = y + (yy << 3);
        float v = t[x][nl];
        __half h, l; split_h(v, h, l);
        size_t o = (size_t)off + (size_t)(n0 + nl) * K + k0 + x;
        Thi[o] = h; Tlo[o] = l;
    }
}

// ======= concat q,k,v biases =======
__global__ void biascat(const float* __restrict__ bq, const float* __restrict__ bk,
                        const float* __restrict__ bv, float* __restrict__ bqkv) {
    int i = threadIdx.x;
    float v;
    if (i < 256) v = bq[i];
    else if (i < 512) v = bk[i - 256];
    else v = bv[i - 512];
    bqkv[i] = v;
}

// ============= elementwise fp32 -> fp16 =============
struct alignas(16) HF8 { __half h[8]; };
struct alignas(8)  HF4 { __half h[4]; };
__global__ void cvth(const float* __restrict__ in, __half* __restrict__ outh,
                     size_t n8) {
    size_t i = (size_t)blockIdx.x * blockDim.x + threadIdx.x;
    if (i >= n8) return;
    const float4* p = (const float4*)(in + i * 8);
    float4 a = p[0], b = p[1];
    float v[8] = {a.x,a.y,a.z,a.w,b.x,b.y,b.z,b.w};
    HF8 H;
#pragma unroll
    for (int j = 0; j < 8; ++j) H.h[j] = __float2half_rn(v[j]);
    *(HF8*)(outh + i * 8) = H;
}

// ==== fused: feature (B,C,H,W) -> window order -> LayerNorm -> fp16 ====
__global__ void __launch_bounds__(256)
wln(const float* __restrict__ feat, const float* __restrict__ g,
    const float* __restrict__ be, __half* __restrict__ outh) {
    __shared__ __align__(16) float tile[32][264];
    const int b   = blockIdx.y;
    const int hw0 = blockIdx.x << 5;
    const int x = threadIdx.x & 31;
    const int y = threadIdx.x >> 5;
    const float* src = feat + (size_t)b * CH * HWTOK + hw0 + x;
#pragma unroll 8
    for (int it = 0; it < 32; ++it) {
        int c = (it << 3) + y;
        tile[x][c] = src[(size_t)c * HWTOK];
    }
    __syncthreads();

    const int lane = threadIdx.x & 31;
    const int w    = threadIdx.x >> 5;
#pragma unroll
    for (int it = 0; it < 4; ++it) {
        int t = (it << 3) + w;
        float4 a4 = *(const float4*)&tile[t][lane * 8];
        float4 b4 = *(const float4*)&tile[t][lane * 8 + 4];
        float v[8] = {a4.x,a4.y,a4.z,a4.w,b4.x,b4.y,b4.z,b4.w};
        float s = 0.f, s2 = 0.f;
#pragma unroll
        for (int j = 0; j < 8; ++j) { s += v[j]; s2 += v[j]*v[j]; }
#pragma unroll
        for (int off = 16; off; off >>= 1) {
            s  += __shfl_xor_sync(0xffffffffu, s,  off);
            s2 += __shfl_xor_sync(0xffffffffu, s2, off);
        }
        float mu  = s * (1.0f/256.0f);
        float var = s2 * (1.0f/256.0f) - mu*mu;
        float r = rsqrtf(var + 1e-5f);
        float4 g0 = *(const float4*)(g + lane*8);
        float4 g1 = *(const float4*)(g + lane*8 + 4);
        float4 e0 = *(const float4*)(be + lane*8);
        float4 e1 = *(const float4*)(be + lane*8 + 4);
        float gg[8] = {g0.x,g0.y,g0.z,g0.w,g1.x,g1.y,g1.z,g1.w};
        float bb[8] = {e0.x,e0.y,e0.z,e0.w,e1.x,e1.y,e1.z,e1.w};
        HF8 H;
#pragma unroll
        for (int j = 0; j < 8; ++j)
            H.h[j] = __float2half_rn((v[j] - mu) * r * gg[j] + bb[j]);
        int hw = hw0 + t;
        int hh = hw >> 7, wp = hw & 127;
        int m = (((b << 8) + ((hh >> 3) << 4) + (wp >> 3)) << 6)
              + ((hh & 7) << 3) + (wp & 7);
        *(HF8*)(outh + (size_t)m * CH + lane*8) = H;
    }
}

// ============= LayerNorm(C=256) -> fp16, 32 thr/row ====
__global__ void __launch_bounds__(256)
ln256_h(const float* __restrict__ in, const float* __restrict__ g,
        const float* __restrict__ be, __half* __restrict__ outh) {
    const int row  = (blockIdx.x << 3) + (threadIdx.x >> 5);
    const int lane = threadIdx.x & 31;
    const float* p = in + (size_t)row * CH + lane * 8;
    float4 a = *(const float4*)p;
    float4 b = *(const float4*)(p + 4);
    float v[8] = {a.x,a.y,a.z,a.w,b.x,b.y,b.z,b.w};
    float s = 0.f, s2 = 0.f;
#pragma unroll
    for (int j = 0; j < 8; ++j) { s += v[j]; s2 += v[j]*v[j]; }
#pragma unroll
    for (int off = 16; off; off >>= 1) {
        s  += __shfl_xor_sync(0xffffffffu, s,  off);
        s2 += __shfl_xor_sync(0xffffffffu, s2, off);
    }
    float mu  = s * (1.0f/256.0f);
    float var = s2 * (1.0f/256.0f) - mu*mu;
    float r = rsqrtf(var + 1e-5f);
    float4 g0 = *(const float4*)(g + lane*8);
    float4 g1 = *(const float4*)(g + lane*8 + 4);
    float4 b0 = *(const float4*)(be + lane*8);
    float4 b1 = *(const float4*)(be + lane*8 + 4);
    float gg[8] = {g0.x,g0.y,g0.z,g0.w,g1.x,g1.y,g1.z,g1.w};
    float bb[8] = {b0.x,b0.y,b0.z,b0.w,b1.x,b1.y,b1.z,b1.w};
    HF8 H;
#pragma unroll
    for (int j = 0; j < 8; ++j)
        H.h[j] = __float2half_rn((v[j] - mu) * r * gg[j] + bb[j]);
    *(HF8*)(outh + (size_t)row * CH + lane*8) = H;
}

// ===== persistent fp16 GEMM: cross-tile pipeline + deferred epilogue =======
// A: fp16 row-major MxK; Bh/Bl: fp16 row-major NxK (=W^T hi/lo).
// Per CTA: loop over tiles (stride PGRID). TMEM = 2x128-col accumulators;
// tile t -> buffer t&1; epilogue(t-1) overlaps tile t's loads/MMAs.
// Chunk commits -> mbar[g&1] (wait g-2 at parity ((g-2)>>1)&1, R14-validated).
// Tile completion -> mbar2[t&1] (wait at parity ((t)>>1)&1).
// MODE 0: C = acc + bias                      (fp32)
// MODE 1: Ch = fp16(gelu(acc + bias))
// MODE 2: C = acc + bias + add                (fp32)
// MODE 3: C[t(m)] = acc + bias + add[t(m)]    (fp32, window->spatial scatter)
#define OFF_ST    1024
#define STAGE_SZ  49152
#define TG_SMEM   (1024 + 2*STAGE_SZ)   // 99328

__device__ __forceinline__ size_t out_row(int m, int N, bool scatter) {
    if (scatter) {
        int b   = m >> 14;
        int rem = m & 16383;
        int wib = rem >> 6;
        int pp  = rem & 63;
        int t = (b << 14)
              + ((((wib >> 4) << 3) + (pp >> 3)) << 7)
              + ((wib & 15) << 3) + (pp & 7);
        return (size_t)t * N;
    }
    return (size_t)m * N;
}

template<int MODE>
__global__ void __launch_bounds__(256, 2) __cluster_dims__(1, 1, 1)
tgemm(const __half* __restrict__ A,
      const __half* __restrict__ Bh, const __half* __restrict__ Bl,
      const float* __restrict__ bias, const float* __restrict__ add,
      float* __restrict__ C, __half* __restrict__ Ch, int K, int N,
      int ntiles, int nx) {
#if HAS_TCGEN05
    extern __shared__ char smem[];
    const uint32_t sb = smem_to_u32(smem);
    const int tid = threadIdx.x;

    if (tid < 32) {
        TCGEN05_ALLOC(sb + 0, 256);
        TCGEN05_RELINQUISH();
    }
    if (tid == 0) {
        MBARRIER_INIT(sb + 16, 1);     // mbar0 (even chunks)
        MBARRIER_INIT(sb + 24, 1);     // mbar1 (odd chunks)
        MBARRIER_INIT(sb + 32, 1);     // mbar2_0 (even tiles)
        MBARRIER_INIT(sb + 40, 1);     // mbar2_1 (odd tiles)
    }
    __syncthreads();
    uint32_t tb;
    asm volatile("ld.shared.b32 %0, [%1];" : "=r"(tb) : "r"(sb + 0));

    // ---- hoisted per-thread layout (tile-invariant) ----
    uint32_t swOff[4];
    int rowI[4], colI[4];
#pragma unroll
    for (int i = 0; i < 4; ++i) {
        int vv  = tid + (i << 8);
        rowI[i] = vv >> 3;
        colI[i] = (vv & 7) << 3;     // col element offset (x8 halfs)
        swOff[i] = SMEM_SWIZZLE_128B((uint32_t)(rowI[i] * 128 + (vv & 7) * 16));
    }
    const int wg   = tid >> 7;
    const int sub  = (tid >> 5) & 3;
    const int lane = tid & 31;
    const int erow = (sub << 5) + lane;

    const int nc = K >> 6;
    uint4 rA[4], rBh[4], rBl[4];
    const __half *tA[4], *tBh[4], *tBl[4];

    auto set_tile_ptrs = [&](int bm, int bn) {
#pragma unroll
        for (int i = 0; i < 4; ++i) {
            tA[i]  = A  + (size_t)(bm + rowI[i]) * K + colI[i];
            tBh[i] = Bh + (size_t)(bn + rowI[i]) * K + colI[i];
            tBl[i] = Bl + (size_t)(bn + rowI[i]) * K + colI[i];
        }
    };
    auto ldg_chunk = [&](int kc) {
        const int ko = kc << 6;
#pragma unroll
        for (int i = 0; i < 4; ++i) {
            rA[i]  = *(const uint4*)(tA[i]  + ko);
            rBh[i] = *(const uint4*)(tBh[i] + ko);
            rBl[i] = *(const uint4*)(tBl[i] + ko);
        }
    };
    auto sts_chunk = [&](int g) {
        char* buf = smem + OFF_ST + (size_t)(g & 1) * STAGE_SZ;
#pragma unroll
        for (int i = 0; i < 4; ++i) {
            *(uint4*)(buf + 0*16384 + swOff[i]) = rA[i];
            *(uint4*)(buf + 1*16384 + swOff[i]) = rBh[i];
            *(uint4*)(buf + 2*16384 + swOff[i]) = rBl[i];
        }
    };
    auto issue_mma = [&](int g, int kc, uint32_t accOff, bool last_in_tile) {
        if (tid < 32) {
            if (elect_one_pred()) {
                uint32_t base = sb + OFF_ST + (uint32_t)(g & 1) * STAGE_SZ;
                uint64_t da  = MAKE_SMEM_DESC(base);
                uint64_t dbh = MAKE_SMEM_DESC(base + 16384);
                uint64_t dbl = MAKE_SMEM_DESC(base + 32768);
                uint32_t first = (kc == 0) ? 0u : 1u;
#pragma unroll
                for (int ks = 0; ks < 4; ++ks)
                    mma_f16_ss(tb + accOff, da + ks*2, dbh + ks*2, GEMM_IDESC,
                               (ks == 0) ? first : 1u);
#pragma unroll
                for (int ks = 0; ks < 4; ++ks)
                    mma_f16_ss(tb + accOff, da + ks*2, dbl + ks*2, GEMM_IDESC, 1u);
                TCGEN05_COMMIT(sb + 16 + ((uint32_t)(g & 1) << 3));
                if (last_in_tile)
                    TCGEN05_COMMIT(sb + 32 + ((uint32_t)((accOff >> 7) & 1) << 3));
            }
        }
    };
    auto epilogue = [&](int tcnt, int e_bm, int e_bn) {
        // wait tile tcnt's MMAs, then write out from acc buffer tcnt&1
        MBARRIER_WAIT_PARITY(sb + 32 + ((uint32_t)(tcnt & 1) << 3),
                             (tcnt >> 1) & 1);
        TCGEN05_FENCE_AFTER();
        const uint32_t accb = tb + ((uint32_t)(tcnt & 1) << 7);
        const int m = e_bm + erow;
        size_t orow = out_row(m, N, MODE == 3);
        const int ncol = e_bn + wg * 64;
#pragma unroll
        for (int half = 0; half < 2; ++half) {
            uint32_t dreg[32];
            TCGEN05_LD_X32(dreg, accb + wg * 64 + half * 32);
            TCGEN05_WAIT_LD();
            const int cbase = half * 32;
            if (MODE == 1) {
                __half* ph = Ch + orow + ncol + cbase;
#pragma unroll
                for (int c8 = 0; c8 < 4; ++c8) {
                    HF8 H;
#pragma unroll
                    for (int j = 0; j < 8; ++j) {
                        float v = __uint_as_float(dreg[c8*8 + j])
                                + bias[ncol + cbase + c8*8 + j];
                        H.h[j] = __float2half_rn(gelu_f(v));
                    }
                    *(HF8*)(ph + c8*8) = H;
                }
            } else {
                float* pc = C + orow + ncol + cbase;
                const float* pa = (MODE >= 2) ? (add + orow + ncol + cbase) : nullptr;
#pragma unroll
                for (int c4 = 0; c4 < 8; ++c4) {
                    float vv[4];
#pragma unroll
                    for (int j = 0; j < 4; ++j)
                        vv[j] = __uint_as_float(dreg[c4*4 + j])
                              + bias[ncol + cbase + c4*4 + j];
                    if (MODE >= 2) {
                        float4 a4 = *(const float4*)(pa + c4*4);
                        vv[0] += a4.x; vv[1] += a4.y; vv[2] += a4.z; vv[3] += a4.w;
                    }
                    float4 o4;
                    o4.x = vv[0]; o4.y = vv[1]; o4.z = vv[2]; o4.w = vv[3];
                    *(float4*)(pc + c4*4) = o4;
                }
            }
        }
        TCGEN05_FENCE_BEFORE();
    };

    // ---- persistent tile loop ----
    int g = 0, tcnt = 0;
    int prev_bm = 0, prev_bn = 0;
    for (int tile = blockIdx.x; tile < ntiles; tile += PGRID, ++tcnt) {
        const int bm = (tile / nx) << 7;
        const int bn = (tile % nx) << 7;
        set_tile_ptrs(bm, bn);
        ldg_chunk(0);                      // in flight over epilogue(prev)
        if (tcnt > 0) epilogue(tcnt - 1, prev_bm, prev_bn);
        for (int kc = 0; kc < nc; ++kc, ++g) {
            if (g >= 2)
                MBARRIER_WAIT_PARITY(sb + 16 + ((uint32_t)(g & 1) << 3),
                                     ((g - 2) >> 1) & 1);
            sts_chunk(g);
            if (kc + 1 < nc) ldg_chunk(kc + 1);
            __syncthreads();
            FENCE_PROXY_ASYNC();
            issue_mma(g, kc, (uint32_t)(tcnt & 1) << 7, kc == nc - 1);
        }
        prev_bm = bm; prev_bn = bn;
    }
    if (tcnt > 0) epilogue(tcnt - 1, prev_bm, prev_bn);

    __syncthreads();
    if (tid < 32) TCGEN05_DEALLOC(tb, 256);
#else
    // ---- generic-arch fallback (never selected at runtime) ----
    const int tid = threadIdx.x;
    for (int tile = blockIdx.x; tile < ntiles; tile += PGRID) {
        const int bm = (tile / nx) << 7;
        const int bn = (tile % nx) << 7;
        for (int idx = tid; idx < 128 * 128; idx += 256) {
            int r = idx >> 7, c = idx & 127;
            int m = bm + r, n = bn + c;
            float acc = 0.f;
            for (int k = 0; k < K; ++k) {
                float av = __half2float(A[(size_t)m * K + k]);
                float bv = __half2float(Bh[(size_t)n * K + k]) +
                           __half2float(Bl[(size_t)n * K + k]);
                acc = fmaf(av, bv, acc);
            }
            size_t orow = out_row(m, N, MODE == 3);
            float v = acc + bias[n];
            if (MODE == 1) {
                Ch[orow + n] = __float2half_rn(gelu_f(v));
            } else {
                if (MODE >= 2) v += add[orow + n];
                C[orow + n] = v;
            }
        }
    }
#endif
}

// ============= window attention (f32x2) on fused qkv, o -> fp16 ============
__global__ void __launch_bounds__(128)
attn_kernel(const float* __restrict__ qkv, const int* __restrict__ rel_idx,
            const float* __restrict__ rpb, __half* __restrict__ oh) {
    const int bx   = blockIdx.x;
    const int widx = bx >> 3;
    const int h    = bx & 7;
    __shared__ __align__(16) float qs[64][33];
    __shared__ __align__(16) float kst[32][68];
    __shared__ __align__(16) float vs[64][34];
    __shared__ __align__(16) float S[64][65];
    const int tid = threadIdx.x;

    const size_t ibase = (size_t)widx * WTOK * QKV_STR + h * HDIM;
    const size_t obase = (size_t)widx * WTOK * CH + h * HDIM;
#pragma unroll
    for (int t = tid; t < 512; t += 128) {
        int r = t >> 3, s = (t & 7) << 2;
        const float* rowp = qkv + ibase + (size_t)r * QKV_STR + s;
        float4 qv = *(const float4*)(rowp);
        float4 kv = *(const float4*)(rowp + 256);
        float4 vv = *(const float4*)(rowp + 512);
        qs[r][s] = qv.x; qs[r][s+1] = qv.y; qs[r][s+2] = qv.z; qs[r][s+3] = qv.w;
        kst[s+0][r] = kv.x; kst[s+1][r] = kv.y; kst[s+2][r] = kv.z; kst[s+3][r] = kv.w;
        vs[r][s] = vv.x; vs[r][s+1] = vv.y; vs[r][s+2] = vv.z; vs[r][s+3] = vv.w;
    }
    __syncthreads();

    const int ty = tid >> 3;
    const int tx = tid & 7;
    const float scale = 0.17677669529663687f;

#if HAS_TCGEN05
    uint64_t acc2[4][4];
#pragma unroll
    for (int i = 0; i < 4; ++i)
#pragma unroll
        for (int j = 0; j < 4; ++j) acc2[i][j] = 0ull;
#pragma unroll 4
    for (int d = 0; d < HDIM; ++d) {
        uint64_t kf2[4], qf2[4];
#pragma unroll
        for (int j = 0; j < 4; ++j)
            kf2[j] = *(const uint64_t*)&kst[d][(tx << 3) + (j << 1)];
#pragma unroll
        for (int i = 0; i < 4; ++i) {
            float qv = qs[(ty << 2) + i][d];
            qf2[i] = pack2(qv, qv);
        }
#pragma unroll
        for (int i = 0; i < 4; ++i)
#pragma unroll
            for (int j = 0; j < 4; ++j)
                acc2[i][j] = fma2(qf2[i], kf2[j], acc2[i][j]);
    }
#pragma unroll
    for (int i = 0; i < 4; ++i) {
        int ii = (ty << 2) + i;
#pragma unroll
        for (int j = 0; j < 4; ++j) {
            float a0, a1; unpack2(acc2[i][j], a0, a1);
            int jj = (tx << 3) + (j << 1);
            int r0 = rel_idx[(ii << 6) + jj];
            int r1 = rel_idx[(ii << 6) + jj + 1];
            S[ii][jj]     = a0 * scale + rpb[r0 * NHEAD + h];
            S[ii][jj + 1] = a1 * scale + rpb[r1 * NHEAD + h];
        }
    }
#else
    float acc[4][8];
#pragma unroll
    for (int i = 0; i < 4; ++i)
#pragma unroll
        for (int j = 0; j < 8; ++j) acc[i][j] = 0.f;
#pragma unroll 8
    for (int d = 0; d < HDIM; ++d) {
        float qf[4], kf[8];
#pragma unroll
        for (int i = 0; i < 4; ++i) qf[i] = qs[(ty << 2) + i][d];
#pragma unroll
        for (int j = 0; j < 8; ++j) kf[j] = kst[d][(tx << 3) + j];
#pragma unroll
        for (int i = 0; i < 4; ++i)
#pragma unroll
            for (int j = 0; j < 8; ++j)
                acc[i][j] = fmaf(qf[i], kf[j], acc[i][j]);
    }
#pragma unroll
    for (int i = 0; i < 4; ++i) {
        int ii = (ty << 2) + i;
#pragma unroll
        for (int j = 0; j < 8; ++j) {
            int jj = (tx << 3) + j;
            int ridx = rel_idx[(ii << 6) + jj];
            S[ii][jj] = acc[i][j] * scale + rpb[ridx * NHEAD + h];
        }
    }
#endif
    __syncthreads();

    // ---- softmax: 2 threads per row ----
    {
        const int rr = tid >> 1, hf = (tid & 1) << 5;
        float mx = -1e30f;
#pragma unroll 8
        for (int j = 0; j < 32; ++j) mx = fmaxf(mx, S[rr][hf + j]);
        mx = fmaxf(mx, __shfl_xor_sync(0xffffffffu, mx, 1));
        float sum = 0.f;
#pragma unroll 8
        for (int j = 0; j < 32; ++j) {
            float e = __expf(S[rr][hf + j] - mx);
            S[rr][hf + j] = e;
            sum += e;
        }
        sum += __shfl_xor_sync(0xffffffffu, sum, 1);
        float inv = 1.0f / sum;
#pragma unroll 8
        for (int j = 0; j < 32; ++j) S[rr][hf + j] *= inv;
    }
    __syncthreads();

    // ---- O = P @ V ----
    const int dx = tid & 7;
#if HAS_TCGEN05
    uint64_t oacc2[4][2];
#pragma unroll
    for (int i = 0; i < 4; ++i) { oacc2[i][0] = 0ull; oacc2[i][1] = 0ull; }
#pragma unroll 4
    for (int mrow = 0; mrow < 64; ++mrow) {
        uint64_t vf2[2], pf2[4];
        vf2[0] = *(const uint64_t*)&vs[mrow][(dx << 2)];
        vf2[1] = *(const uint64_t*)&vs[mrow][(dx << 2) + 2];
#pragma unroll
        for (int i = 0; i < 4; ++i) {
            float pv = S[(ty << 2) + i][mrow];
            pf2[i] = pack2(pv, pv);
        }
#pragma unroll
        for (int i = 0; i < 4; ++i) {
            oacc2[i][0] = fma2(pf2[i], vf2[0], oacc2[i][0]);
            oacc2[i][1] = fma2(pf2[i], vf2[1], oacc2[i][1]);
        }
    }
#pragma unroll
    for (int i = 0; i < 4; ++i) {
        size_t orow = obase + (size_t)((ty << 2) + i) * CH + (dx << 2);
        float o0, o1, o2, o3;
        unpack2(oacc2[i][0], o0, o1);
        unpack2(oacc2[i][1], o2, o3);
        HF4 H;
        H.h[0] = __float2half_rn(o0); H.h[1] = __float2half_rn(o1);
        H.h[2] = __float2half_rn(o2); H.h[3] = __float2half_rn(o3);
        *(HF4*)(oh + orow) = H;
    }
#else
    float oacc[4][4];
#pragma unroll
    for (int i = 0; i < 4; ++i)
#pragma unroll
        for (int d = 0; d < 4; ++d) oacc[i][d] = 0.f;
#pragma unroll 8
    for (int mrow = 0; mrow < 64; ++mrow) {
        float pf[4], vf[4];
#pragma unroll
        for (int i = 0; i < 4; ++i) pf[i] = S[(ty << 2) + i][mrow];
#pragma unroll
        for (int d = 0; d < 4; ++d) vf[d] = vs[mrow][(dx << 2) + d];
#pragma unroll
        for (int i = 0; i < 4; ++i)
#pragma unroll
            for (int d = 0; d < 4; ++d)
                oacc[i][d] = fmaf(pf[i], vf[d], oacc[i][d]);
    }
#pragma unroll
    for (int i = 0; i < 4; ++i) {
        size_t orow = obase + (size_t)((ty << 2) + i) * CH + (dx << 2);
        HF4 H;
#pragma unroll
        for (int d = 0; d < 4; ++d) H.h[d] = __float2half_rn(oacc[i][d]);
        *(HF4*)(oh + orow) = H;
    }
#endif
}

// ==========================================================================
extern "C" void kernel_launch(void* const* d_in, const int* in_sizes, int n_in,
                              void* d_out, int out_size) {
    const float* x       = (const float*)d_in[0];
    const float* feature = (const float*)d_in[1];
    const float* Wq  = (const float*)d_in[2];
    const float* bq  = (const float*)d_in[3];
    const float* Wk  = (const float*)d_in[4];
    const float* bk  = (const float*)d_in[5];
    const float* Wv  = (const float*)d_in[6];
    const float* bv  = (const float*)d_in[7];
    const float* Wo  = (const float*)d_in[8];
    const float* bo  = (const float*)d_in[9];
    const float* rpb = (const float*)d_in[10];
    const float* g1  = (const float*)d_in[11];
    const float* be1 = (const float*)d_in[12];
    const float* g2  = (const float*)d_in[13];
    const float* be2 = (const float*)d_in[14];
    const float* Wm1 = (const float*)d_in[15];
    const float* bm1 = (const float*)d_in[16];
    const float* Wm2 = (const float*)d_in[17];
    const float* bm2 = (const float*)d_in[18];
    const float* Wu1 = (const float*)d_in[19];
    const float* bu1 = (const float*)d_in[20];
    const float* Wu2 = (const float*)d_in[21];
    const float* bu2 = (const float*)d_in[22];
    const int*   rel = (const int*)d_in[23];
    float* out = (float*)d_out;

    cudaFuncSetAttribute(tgemm<0>, cudaFuncAttributeMaxDynamicSharedMemorySize, TG_SMEM);
    cudaFuncSetAttribute(tgemm<1>, cudaFuncAttributeMaxDynamicSharedMemorySize, TG_SMEM);
    cudaFuncSetAttribute(tgemm<2>, cudaFuncAttributeMaxDynamicSharedMemorySize, TG_SMEM);
    cudaFuncSetAttribute(tgemm<3>, cudaFuncAttributeMaxDynamicSharedMemorySize, TG_SMEM);

    void *p;
    #define SYM(name, var) cudaGetSymbolAddress(&p, name); auto* var = decltype(&name[0])(p)
    SYM(g_qkv, qkv);
    SYM(g_unary, unary); SYM(g_x2, x2); SYM(g_bqkv, bqkv);
    SYM(g_xh, xh); SYM(g_th, th); SYM(g_nh, nh);
    SYM(g_oh, oh); SYM(g_lh, lh); SYM(g_hh, hh);
    SYM(g_wthi, wthi); SYM(g_wtlo, wtlo);
    #undef SYM

    // ---- weight transpose + fp16 split; qkv bias concat ----
    wprep_all<<<dim3(32, 32, 8), dim3(32, 8)>>>(Wq, Wk, Wv, Wo, Wu1, Wu2, Wm1, Wm2,
                                                wthi, wtlo);
    biascat<<<1, 768>>>(bq, bk, bv, bqkv);

    // ---- input -> fp16 ----
    cvth<<<(MTOK * CH / 8 + 255) / 256, 256>>>(x, xh, (size_t)MTOK * CH / 8);

    // persistent grids: (ntiles, nx)
    // N=256: nx=2, 2048 tiles; qkv: nx=6, 6144; M1: nx=8, 8192; M2: nx=2, 2048
    // unary = gelu(x@Wu1+bu1)@Wu2 + bu2
    tgemm<1><<<PGRID, 256, TG_SMEM>>>(xh, wthi + WOFF_U1, wtlo + WOFF_U1,
                                      bu1, nullptr, nullptr, th, 256, 256, 2048, 2);
    tgemm<0><<<PGRID, 256, TG_SMEM>>>(th, wthi + WOFF_U2, wtlo + WOFF_U2,
                                      bu2, nullptr, unary, nullptr, 256, 256, 2048, 2);

    // feature -> windows + LN1 fused -> fp16
    wln<<<dim3(HWTOK / 32, BATCH), 256>>>(feature, g1, be1, nh);

    // fused q,k,v projection (N=768)
    tgemm<0><<<PGRID, 256, TG_SMEM>>>(nh, wthi + WOFF_Q, wtlo + WOFF_Q,
                                      bqkv, nullptr, qkv, nullptr, 256, QKV_STR, 6144, 6);

    // attention -> o (fp16)
    attn_kernel<<<NWIN * NHEAD, 128>>>(qkv, rel, rpb, oh);

    // x2 = unary + scatter(o@Wo + bo)
    tgemm<3><<<PGRID, 256, TG_SMEM>>>(oh, wthi + WOFF_O, wtlo + WOFF_O,
                                      bo, unary, x2, nullptr, 256, 256, 2048, 2);

    // MLP: out = x2 + gelu(LN(x2)@Wm1+bm1)@Wm2 + bm2
    ln256_h<<<MTOK / 8, 256>>>(x2, g2, be2, lh);
    tgemm<1><<<PGRID, 256, TG_SMEM>>>(lh, wthi + WOFF_M1, wtlo + WOFF_M1,
                                      bm1, nullptr, nullptr, hh, 256, 1024, 8192, 8);
    tgemm<2><<<PGRID, 256, TG_SMEM>>>(hh, wthi + WOFF_M2, wtlo + WOFF_M2,
                                      bm2, x2, out, nullptr, 1024, 256, 2048, 2);
}

// round 16
// speedup vs baseline: 1.1403x; 1.1403x over previous
#include <cuda_runtime.h>
#include <cuda_bf16.h>
#include <cuda_fp16.h>
#include <math.h>
#include <cstdint>

// Problem constants
#define BATCH   8
#define CH      256
#define HH      128
#define WW_     128
#define HWTOK   (HH*WW_)            // 16384
#define MTOK    (BATCH*HWTOK)       // 131072
#define HID     1024
#define NHEAD   8
#define HDIM    32
#define WSZ     8
#define WTOK    (WSZ*WSZ)           // 64
#define NWIN    (MTOK/WTOK)         // 2048
#define QKV_STR 768

#if defined(__CUDA_ARCH__) && (defined(__CUDA_ARCH_FEAT_SM103_ALL) || \
    (defined(__CUDA_ARCH_SPECIFIC__)) || (defined(__CUDA_ARCH_FAMILY_SPECIFIC__)))
#define HAS_TCGEN05 1
#else
#define HAS_TCGEN05 0
#endif

// ===================== PTX helpers (inlined, sm_103a) =====================
__device__ __forceinline__ uint32_t elect_one_pred() {
    uint32_t pred;
    asm volatile("{\n\t.reg .pred p;\n\telect.sync _|p, 0xFFFFFFFF;\n\t"
                 "selp.b32 %0, 1, 0, p;\n\t}" : "=r"(pred));
    return pred;
}
__device__ __forceinline__ uint32_t smem_to_u32(const void* p) {
    uint32_t a;
    asm("{ .reg .u64 t; cvta.to.shared.u64 t, %1; cvt.u32.u64 %0, t; }" : "=r"(a) : "l"(p));
    return a;
}
static constexpr uint64_t SMEM_DESC_BASE_SW128 =
    (uint64_t(2) << 61) | (uint64_t(1) << 46) | (uint64_t(64) << 32) | (uint64_t(1) << 16);
#define MAKE_SMEM_DESC(base_addr) \
    (SMEM_DESC_BASE_SW128 | ((uint64_t)((base_addr) >> 4) & 0x3FFF))
#define SMEM_SWIZZLE_128B(off) ((off) ^ (((off) >> 3) & 0x70))

#if HAS_TCGEN05
#define TCGEN05_ALLOC(smem_result_addr, nCols) \
    asm volatile("tcgen05.alloc.cta_group::1.sync.aligned.shared::cta.b32 [%0], %1;" \
        :: "r"((uint32_t)(smem_result_addr)), "r"((uint32_t)(nCols)) : "memory")
#define TCGEN05_DEALLOC(tmem_addr, nCols) \
    asm volatile("tcgen05.dealloc.cta_group::1.sync.aligned.b32 %0, %1;" \
        :: "r"(tmem_addr), "r"((uint32_t)(nCols)))
#define TCGEN05_RELINQUISH() \
    asm volatile("tcgen05.relinquish_alloc_permit.cta_group::1.sync.aligned;")
#define TCGEN05_COMMIT(mbar) \
    asm volatile("tcgen05.commit.cta_group::1.mbarrier::arrive::one.shared::cluster.b64 [%0];" \
        :: "r"((uint32_t)(mbar)) : "memory")
#define TCGEN05_FENCE_AFTER() \
    asm volatile("tcgen05.fence::after_thread_sync;" ::: "memory")
#define TCGEN05_FENCE_BEFORE() \
    asm volatile("tcgen05.fence::before_thread_sync;" ::: "memory")
#define TCGEN05_WAIT_LD() \
    asm volatile("tcgen05.wait::ld.sync.aligned;" ::: "memory")
#define TCGEN05_LD_X32(r, addr) \
    asm volatile("tcgen05.ld.sync.aligned.32x32b.x32.b32 " \
        "{%0, %1, %2, %3, %4, %5, %6, %7, %8, %9, %10, %11, %12, %13, %14, %15, " \
        " %16, %17, %18, %19, %20, %21, %22, %23, %24, %25, %26, %27, %28, %29, %30, %31}, [%32];" \
        : "=r"((r)[0]),  "=r"((r)[1]),  "=r"((r)[2]),  "=r"((r)[3]), \
          "=r"((r)[4]),  "=r"((r)[5]),  "=r"((r)[6]),  "=r"((r)[7]), \
          "=r"((r)[8]),  "=r"((r)[9]),  "=r"((r)[10]), "=r"((r)[11]), \
          "=r"((r)[12]), "=r"((r)[13]), "=r"((r)[14]), "=r"((r)[15]), \
          "=r"((r)[16]), "=r"((r)[17]), "=r"((r)[18]), "=r"((r)[19]), \
          "=r"((r)[20]), "=r"((r)[21]), "=r"((r)[22]), "=r"((r)[23]), \
          "=r"((r)[24]), "=r"((r)[25]), "=r"((r)[26]), "=r"((r)[27]), \
          "=r"((r)[28]), "=r"((r)[29]), "=r"((r)[30]), "=r"((r)[31]) \
        : "r"(addr))
__device__ __forceinline__ void mma_f16_ss(uint32_t d, uint64_t a, uint64_t b,
                                           uint32_t idesc, uint32_t acc) {
    asm volatile(
        "{\n\t.reg .pred p;\n\tsetp.ne.u32 p, %4, 0;\n\t"
        "tcgen05.mma.cta_group::1.kind::f16 [%0], %1, %2, %3, {%5, %5, %5, %5}, p;\n\t}"
        :: "r"(d), "l"(a), "l"(b), "r"(idesc), "r"(acc), "r"(0u) : "memory");
}
// packed f32x2 FMA
__device__ __forceinline__ uint64_t pack2(float x, float y) {
    uint64_t r; asm("mov.b64 %0, {%1, %2};" : "=l"(r) : "f"(x), "f"(y)); return r;
}
__device__ __forceinline__ void unpack2(uint64_t v, float& x, float& y) {
    asm("mov.b64 {%0, %1}, %2;" : "=f"(x), "=f"(y) : "l"(v));
}
__device__ __forceinline__ uint64_t fma2(uint64_t a, uint64_t b, uint64_t c) {
    uint64_t d; asm("fma.rn.f32x2 %0, %1, %2, %3;" : "=l"(d) : "l"(a), "l"(b), "l"(c));
    return d;
}
#endif // HAS_TCGEN05

#define FENCE_PROXY_ASYNC() \
    asm volatile("fence.proxy.async.shared::cta;" ::: "memory")
#define MBARRIER_INIT(mbar, cnt) \
    asm volatile("mbarrier.init.shared.b64 [%0], %1;" \
        :: "r"((uint32_t)(mbar)), "r"((uint32_t)(cnt)) : "memory")
#define MBARRIER_WAIT_PARITY(mbar, parity) do { \
    uint32_t _m = (uint32_t)(mbar); uint32_t _p = (uint32_t)(parity); uint32_t _d; \
    asm volatile("{\n\t.reg .pred p;\n\t" \
        "mbarrier.try_wait.parity.acquire.cta.shared::cta.b64 p, [%1], %2;\n\t" \
        "selp.b32 %0, 1, 0, p;\n\t}" : "=r"(_d) : "r"(_m), "r"(_p) : "memory"); \
    if (!_d) { \
        asm volatile("{\n\t.reg .pred P1;\n\t" \
            "WL_%=:\n\t" \
            "mbarrier.try_wait.parity.acquire.cta.shared::cta.b64 P1, [%0], %1, 0x989680;\n\t" \
            "@P1 bra.uni WD_%=;\n\t" \
            "bra.uni WL_%=;\n\t" \
            "WD_%=:\n\t}" :: "r"(_m), "r"(_p) : "memory"); \
    } \
} while(0)

// idesc: dtype=F32, atype=FP16(0), btype=FP16(0), N=128 (16<<17), M=128 (8<<24)
#define GEMM_IDESC ((1u<<4)|(16u<<17)|(8u<<24))

// ===================== scratch (static device globals) =====================
__device__ float g_unary[(size_t)MTOK*CH];
__device__ float g_x2   [(size_t)MTOK*CH];
__device__ float g_bqkv [QKV_STR];
__device__ __align__(16) __half g_qkvh[(size_t)MTOK*QKV_STR];  // fp16 qkv
__device__ __align__(16) __half g_xh [(size_t)MTOK*CH];
__device__ __align__(16) __half g_th [(size_t)MTOK*CH];
__device__ __align__(16) __half g_nh [(size_t)MTOK*CH];
__device__ __align__(16) __half g_oh [(size_t)MTOK*CH];
__device__ __align__(16) __half g_lh [(size_t)MTOK*CH];
__device__ __align__(16) __half g_hh [(size_t)MTOK*HID];
#define WOFF_Q   0
#define WOFF_K   65536
#define WOFF_V   131072
#define WOFF_O   196608
#define WOFF_U1  262144
#define WOFF_U2  327680
#define WOFF_M1  393216
#define WOFF_M2  655360
__device__ __align__(16) __half g_wthi[917504];
__device__ __align__(16) __half g_wtlo[917504];

__device__ __forceinline__ float gelu_f(float x) {
    return 0.5f * x * (1.0f + erff(x * 0.70710678118654752f));
}
__device__ __forceinline__ void split_h(float v, __half& h, __half& l) {
    h = __float2half_rn(v);
    l = __float2half_rn(v - __half2float(h));
}

// ======= weight prep (all 8 weights, one launch): W(KxN) -> T(NxK) hi/lo ===
__global__ void wprep_all(const float* __restrict__ Wq, const float* __restrict__ Wk,
                          const float* __restrict__ Wv, const float* __restrict__ Wo,
                          const float* __restrict__ Wu1, const float* __restrict__ Wu2,
                          const float* __restrict__ Wm1, const float* __restrict__ Wm2,
                          __half* __restrict__ Thi, __half* __restrict__ Tlo) {
    const float* W; int K, N, off;
    switch (blockIdx.z) {
        case 0: W = Wq;  K = 256;  N = 256;  off = WOFF_Q;  break;
        case 1: W = Wk;  K = 256;  N = 256;  off = WOFF_K;  break;
        case 2: W = Wv;  K = 256;  N = 256;  off = WOFF_V;  break;
        case 3: W = Wo;  K = 256;  N = 256;  off = WOFF_O;  break;
        case 4: W = Wu1; K = 256;  N = 256;  off = WOFF_U1; break;
        case 5: W = Wu2; K = 256;  N = 256;  off = WOFF_U2; break;
        case 6: W = Wm1; K = 256;  N = 1024; off = WOFF_M1; break;
        default:W = Wm2; K = 1024; N = 256;  off = WOFF_M2; break;
    }
    const int n0 = blockIdx.x << 5, k0 = blockIdx.y << 5;
    if (n0 >= N || k0 >= K) return;
    __shared__ float t[32][33];
    const int x = threadIdx.x, y = threadIdx.y;
#pragma unroll
    for (int yy = 0; yy < 4; ++yy) {
        int kl = y + (yy << 3);
        t[kl][x] = W[(size_t)(k0 + kl) * N + n0 + x];
    }
    __syncthreads();
#pragma unroll
    for (int yy = 0; yy < 4; ++yy) {
        int nl = y + (yy << 3);
        float v = t[x][nl];
        __half h, l; split_h(v, h, l);
        size_t o = (size_t)off + (size_t)(n0 + nl) * K + k0 + x;
        Thi[o] = h; Tlo[o] = l;
    }
}

// ======= concat q,k,v biases =======
__global__ void biascat(const float* __restrict__ bq, const float* __restrict__ bk,
                        const float* __restrict__ bv, float* __restrict__ bqkv) {
    int i = threadIdx.x;
    float v;
    if (i < 256) v = bq[i];
    else if (i < 512) v = bk[i - 256];
    else v = bv[i - 512];
    bqkv[i] = v;
}

// ============= elementwise fp32 -> fp16 =============
struct alignas(16) HF8 { __half h[8]; };
struct alignas(8)  HF4 { __half h[4]; };
__global__ void cvth(const float* __restrict__ in, __half* __restrict__ outh,
                     size_t n8) {
    size_t i = (size_t)blockIdx.x * blockDim.x + threadIdx.x;
    if (i >= n8) return;
    const float4* p = (const float4*)(in + i * 8);
    float4 a = p[0], b = p[1];
    float v[8] = {a.x,a.y,a.z,a.w,b.x,b.y,b.z,b.w};
    HF8 H;
#pragma unroll
    for (int j = 0; j < 8; ++j) H.h[j] = __float2half_rn(v[j]);
    *(HF8*)(outh + i * 8) = H;
}

// ==== fused: feature (B,C,H,W) -> window order -> LayerNorm -> fp16 ====
__global__ void __launch_bounds__(256)
wln(const float* __restrict__ feat, const float* __restrict__ g,
    const float* __restrict__ be, __half* __restrict__ outh) {
    __shared__ __align__(16) float tile[32][264];
    const int b   = blockIdx.y;
    const int hw0 = blockIdx.x << 5;
    const int x = threadIdx.x & 31;
    const int y = threadIdx.x >> 5;
    const float* src = feat + (size_t)b * CH * HWTOK + hw0 + x;
#pragma unroll 8
    for (int it = 0; it < 32; ++it) {
        int c = (it << 3) + y;
        tile[x][c] = src[(size_t)c * HWTOK];
    }
    __syncthreads();

    const int lane = threadIdx.x & 31;
    const int w    = threadIdx.x >> 5;
#pragma unroll
    for (int it = 0; it < 4; ++it) {
        int t = (it << 3) + w;
        float4 a4 = *(const float4*)&tile[t][lane * 8];
        float4 b4 = *(const float4*)&tile[t][lane * 8 + 4];
        float v[8] = {a4.x,a4.y,a4.z,a4.w,b4.x,b4.y,b4.z,b4.w};
        float s = 0.f, s2 = 0.f;
#pragma unroll
        for (int j = 0; j < 8; ++j) { s += v[j]; s2 += v[j]*v[j]; }
#pragma unroll
        for (int off = 16; off; off >>= 1) {
            s  += __shfl_xor_sync(0xffffffffu, s,  off);
            s2 += __shfl_xor_sync(0xffffffffu, s2, off);
        }
        float mu  = s * (1.0f/256.0f);
        float var = s2 * (1.0f/256.0f) - mu*mu;
        float r = rsqrtf(var + 1e-5f);
        float4 g0 = *(const float4*)(g + lane*8);
        float4 g1 = *(const float4*)(g + lane*8 + 4);
        float4 e0 = *(const float4*)(be + lane*8);
        float4 e1 = *(const float4*)(be + lane*8 + 4);
        float gg[8] = {g0.x,g0.y,g0.z,g0.w,g1.x,g1.y,g1.z,g1.w};
        float bb[8] = {e0.x,e0.y,e0.z,e0.w,e1.x,e1.y,e1.z,e1.w};
        HF8 H;
#pragma unroll
        for (int j = 0; j < 8; ++j)
            H.h[j] = __float2half_rn((v[j] - mu) * r * gg[j] + bb[j]);
        int hw = hw0 + t;
        int hh = hw >> 7, wp = hw & 127;
        int m = (((b << 8) + ((hh >> 3) << 4) + (wp >> 3)) << 6)
              + ((hh & 7) << 3) + (wp & 7);
        *(HF8*)(outh + (size_t)m * CH + lane*8) = H;
    }
}

// ============= LayerNorm(C=256) -> fp16, 32 thr/row ====
__global__ void __launch_bounds__(256)
ln256_h(const float* __restrict__ in, const float* __restrict__ g,
        const float* __restrict__ be, __half* __restrict__ outh) {
    const int row  = (blockIdx.x << 3) + (threadIdx.x >> 5);
    const int lane = threadIdx.x & 31;
    const float* p = in + (size_t)row * CH + lane * 8;
    float4 a = *(const float4*)p;
    float4 b = *(const float4*)(p + 4);
    float v[8] = {a.x,a.y,a.z,a.w,b.x,b.y,b.z,b.w};
    float s = 0.f, s2 = 0.f;
#pragma unroll
    for (int j = 0; j < 8; ++j) { s += v[j]; s2 += v[j]*v[j]; }
#pragma unroll
    for (int off = 16; off; off >>= 1) {
        s  += __shfl_xor_sync(0xffffffffu, s,  off);
        s2 += __shfl_xor_sync(0xffffffffu, s2, off);
    }
    float mu  = s * (1.0f/256.0f);
    float var = s2 * (1.0f/256.0f) - mu*mu;
    float r = rsqrtf(var + 1e-5f);
    float4 g0 = *(const float4*)(g + lane*8);
    float4 g1 = *(const float4*)(g + lane*8 + 4);
    float4 b0 = *(const float4*)(be + lane*8);
    float4 b1 = *(const float4*)(be + lane*8 + 4);
    float gg[8] = {g0.x,g0.y,g0.z,g0.w,g1.x,g1.y,g1.z,g1.w};
    float bb[8] = {b0.x,b0.y,b0.z,b0.w,b1.x,b1.y,b1.z,b1.w};
    HF8 H;
#pragma unroll
    for (int j = 0; j < 8; ++j)
        H.h[j] = __float2half_rn((v[j] - mu) * r * gg[j] + bb[j]);
    *(HF8*)(outh + (size_t)row * CH + lane*8) = H;
}

// ============= fp16 GEMM: reg-staged double-buffer, 2 mbarriers ============
// (R14-validated pipeline, byte-identical synchronization)
// MODE 0: C = acc + bias                      (fp32)
// MODE 1: Ch = fp16(gelu(acc + bias))
// MODE 2: C = acc + bias + add                (fp32)
// MODE 3: C[t(m)] = acc + bias + add[t(m)]    (fp32, window->spatial scatter)
// MODE 4: Ch = fp16(acc + bias)               (plain fp16)
#define OFF_BIAS  512
#define OFF_ST    1024
#define STAGE_SZ  49152
#define TG_SMEM   (1024 + 2*STAGE_SZ)   // 99328

__device__ __forceinline__ size_t out_row(int m, int N, bool scatter) {
    if (scatter) {
        int b   = m >> 14;
        int rem = m & 16383;
        int wib = rem >> 6;
        int pp  = rem & 63;
        int t = (b << 14)
              + ((((wib >> 4) << 3) + (pp >> 3)) << 7)
              + ((wib & 15) << 3) + (pp & 7);
        return (size_t)t * N;
    }
    return (size_t)m * N;
}

template<int MODE>
__global__ void __launch_bounds__(256, 2) __cluster_dims__(1, 1, 1)
tgemm(const __half* __restrict__ A,
      const __half* __restrict__ Bh, const __half* __restrict__ Bl,
      const float* __restrict__ bias, const float* __restrict__ add,
      float* __restrict__ C, __half* __restrict__ Ch, int K, int N) {
#if HAS_TCGEN05
    extern __shared__ char smem[];
    const uint32_t sb = smem_to_u32(smem);
    const int tid = threadIdx.x;
    const int bm = blockIdx.y << 7;
    const int bn = blockIdx.x << 7;

    if (tid < 32) {
        TCGEN05_ALLOC(sb + 0, 128);
        TCGEN05_RELINQUISH();
    }
    if (tid == 0) {
        MBARRIER_INIT(sb + 16, 1);     // mbar0 (even chunks)
        MBARRIER_INIT(sb + 24, 1);     // mbar1 (odd chunks)
    }
    if (tid >= 128) {
        ((float*)(smem + OFF_BIAS))[tid - 128] = bias[bn + tid - 128];
    }
    __syncthreads();
    uint32_t tb;
    asm volatile("ld.shared.b32 %0, [%1];" : "=r"(tb) : "r"(sb + 0));

    // ---- hoisted per-thread addressing (kc-invariant) ----
    uint32_t swOff[4];
    const __half *pA[4], *pBh[4], *pBl[4];
#pragma unroll
    for (int i = 0; i < 4; ++i) {
        int vv  = tid + (i << 8);
        int row = vv >> 3;
        int c16 = vv & 7;
        swOff[i] = SMEM_SWIZZLE_128B((uint32_t)(row * 128 + c16 * 16));
        pA[i]  = A  + (size_t)(bm + row) * K + c16 * 8;
        pBh[i] = Bh + (size_t)(bn + row) * K + c16 * 8;
        pBl[i] = Bl + (size_t)(bn + row) * K + c16 * 8;
    }

    const int nc = K >> 6;
    uint4 rA[4], rBh[4], rBl[4];

    auto ldg_chunk = [&](int kc) {
        const int ko = kc << 6;
#pragma unroll
        for (int i = 0; i < 4; ++i) {
            rA[i]  = *(const uint4*)(pA[i]  + ko);
            rBh[i] = *(const uint4*)(pBh[i] + ko);
            rBl[i] = *(const uint4*)(pBl[i] + ko);
        }
    };
    auto sts_chunk = [&](int kc) {
        char* buf = smem + OFF_ST + (size_t)(kc & 1) * STAGE_SZ;
#pragma unroll
        for (int i = 0; i < 4; ++i) {
            *(uint4*)(buf + 0*16384 + swOff[i]) = rA[i];
            *(uint4*)(buf + 1*16384 + swOff[i]) = rBh[i];
            *(uint4*)(buf + 2*16384 + swOff[i]) = rBl[i];
        }
    };
    auto issue_mma = [&](int kc) {
        if (tid < 32) {
            if (elect_one_pred()) {
                uint32_t base = sb + OFF_ST + (uint32_t)(kc & 1) * STAGE_SZ;
                uint64_t da  = MAKE_SMEM_DESC(base);
                uint64_t dbh = MAKE_SMEM_DESC(base + 16384);
                uint64_t dbl = MAKE_SMEM_DESC(base + 32768);
                uint32_t first = (kc == 0) ? 0u : 1u;
#pragma unroll
                for (int ks = 0; ks < 4; ++ks)
                    mma_f16_ss(tb, da + ks*2, dbh + ks*2, GEMM_IDESC,
                               (ks == 0) ? first : 1u);
#pragma unroll
                for (int ks = 0; ks < 4; ++ks)
                    mma_f16_ss(tb, da + ks*2, dbl + ks*2, GEMM_IDESC, 1u);
                TCGEN05_COMMIT(sb + 16 + ((uint32_t)(kc & 1) << 3));
            }
        }
    };

    // Pipeline: regs hold chunk kc at top of iteration kc.
    ldg_chunk(0);
    for (int kc = 0; kc < nc; ++kc) {
        if (kc >= 2) {
            MBARRIER_WAIT_PARITY(sb + 16 + ((uint32_t)(kc & 1) << 3),
                                 ((kc - 2) >> 1) & 1);
        }
        sts_chunk(kc);
        if (kc + 1 < nc) ldg_chunk(kc + 1);
        __syncthreads();
        FENCE_PROXY_ASYNC();
        issue_mma(kc);
    }
    if (nc >= 2)
        MBARRIER_WAIT_PARITY(sb + 16 + ((uint32_t)((nc - 2) & 1) << 3),
                             ((nc - 2) >> 1) & 1);
    MBARRIER_WAIT_PARITY(sb + 16 + ((uint32_t)((nc - 1) & 1) << 3),
                         ((nc - 1) >> 1) & 1);
    TCGEN05_FENCE_AFTER();

    // ---------------- epilogue (two 32-reg halves) --------------------------
    const int wg   = tid >> 7;
    const int sub  = (tid >> 5) & 3;
    const int lane = tid & 31;
    const int row  = (sub << 5) + lane;
    const float* biasS = (const float*)(smem + OFF_BIAS) + wg * 64;
    const int m = bm + row;
    size_t orow = out_row(m, N, MODE == 3);
    const int ncol = bn + wg * 64;

#pragma unroll
    for (int half = 0; half < 2; ++half) {
        uint32_t dreg[32];
        TCGEN05_LD_X32(dreg, tb + wg * 64 + half * 32);
        TCGEN05_WAIT_LD();
        const int cbase = half * 32;
        if (MODE == 1 || MODE == 4) {
            __half* ph = Ch + orow + ncol + cbase;
#pragma unroll
            for (int c8 = 0; c8 < 4; ++c8) {
                HF8 H;
#pragma unroll
                for (int j = 0; j < 8; ++j) {
                    float v = __uint_as_float(dreg[c8*8 + j]) + biasS[cbase + c8*8 + j];
                    if (MODE == 1) v = gelu_f(v);
                    H.h[j] = __float2half_rn(v);
                }
                *(HF8*)(ph + c8*8) = H;
            }
        } else {
            float* pc = C + orow + ncol + cbase;
            const float* pa = (MODE >= 2) ? (add + orow + ncol + cbase) : nullptr;
#pragma unroll
            for (int c4 = 0; c4 < 8; ++c4) {
                float vv[4];
#pragma unroll
                for (int j = 0; j < 4; ++j)
                    vv[j] = __uint_as_float(dreg[c4*4 + j]) + biasS[cbase + c4*4 + j];
                if (MODE == 2 || MODE == 3) {
                    float4 a4 = *(const float4*)(pa + c4*4);
                    vv[0] += a4.x; vv[1] += a4.y; vv[2] += a4.z; vv[3] += a4.w;
                }
                float4 o4;
                o4.x = vv[0]; o4.y = vv[1]; o4.z = vv[2]; o4.w = vv[3];
                *(float4*)(pc + c4*4) = o4;
            }
        }
    }
    TCGEN05_FENCE_BEFORE();

    __syncthreads();
    if (tid < 32) TCGEN05_DEALLOC(tb, 128);
#else
    // ---- generic-arch fallback (never selected at runtime) ----
    const int tid = threadIdx.x;
    const int bm = blockIdx.y << 7;
    const int bn = blockIdx.x << 7;
    for (int idx = tid; idx < 128 * 128; idx += 256) {
        int r = idx >> 7, c = idx & 127;
        int m = bm + r, n = bn + c;
        float acc = 0.f;
        for (int k = 0; k < K; ++k) {
            float av = __half2float(A[(size_t)m * K + k]);
            float bv = __half2float(Bh[(size_t)n * K + k]) +
                       __half2float(Bl[(size_t)n * K + k]);
            acc = fmaf(av, bv, acc);
        }
        size_t orow = out_row(m, N, MODE == 3);
        float v = acc + bias[n];
        if (MODE == 1) {
            Ch[orow + n] = __float2half_rn(gelu_f(v));
        } else if (MODE == 4) {
            Ch[orow + n] = __float2half_rn(v);
        } else {
            if (MODE >= 2) v += add[orow + n];
            C[orow + n] = v;
        }
    }
#endif
}

// ============= window attention (f32x2) on fp16 fused qkv, o -> fp16 =======
__global__ void __launch_bounds__(128)
attn_kernel(const __half* __restrict__ qkv, const int* __restrict__ rel_idx,
            const float* __restrict__ rpb, __half* __restrict__ oh) {
    const int bx   = blockIdx.x;
    const int widx = bx >> 3;
    const int h    = bx & 7;
    __shared__ __align__(16) float qs[64][33];
    __shared__ __align__(16) float kst[32][68];
    __shared__ __align__(16) float vs[64][34];
    __shared__ __align__(16) float S[64][65];
    const int tid = threadIdx.x;

    const size_t ibase = (size_t)widx * WTOK * QKV_STR + h * HDIM;
    const size_t obase = (size_t)widx * WTOK * CH + h * HDIM;
    // 64 rows x 32 halfs per array; 8 halfs (16B) per transfer -> 256 iters
#pragma unroll
    for (int t = tid; t < 256; t += 128) {
        int r = t >> 2, s = (t & 3) << 3;
        const __half* rowp = qkv + ibase + (size_t)r * QKV_STR + s;
        HF8 qv = *(const HF8*)(rowp);
        HF8 kv = *(const HF8*)(rowp + 256);
        HF8 vv = *(const HF8*)(rowp + 512);
#pragma unroll
        for (int j = 0; j < 8; ++j) {
            qs[r][s + j]   = __half2float(qv.h[j]);
            kst[s + j][r]  = __half2float(kv.h[j]);
            vs[r][s + j]   = __half2float(vv.h[j]);
        }
    }
    __syncthreads();

    const int ty = tid >> 3;
    const int tx = tid & 7;
    const float scale = 0.17677669529663687f;

#if HAS_TCGEN05
    uint64_t acc2[4][4];
#pragma unroll
    for (int i = 0; i < 4; ++i)
#pragma unroll
        for (int j = 0; j < 4; ++j) acc2[i][j] = 0ull;
#pragma unroll 4
    for (int d = 0; d < HDIM; ++d) {
        uint64_t kf2[4], qf2[4];
#pragma unroll
        for (int j = 0; j < 4; ++j)
            kf2[j] = *(const uint64_t*)&kst[d][(tx << 3) + (j << 1)];
#pragma unroll
        for (int i = 0; i < 4; ++i) {
            float qv = qs[(ty << 2) + i][d];
            qf2[i] = pack2(qv, qv);
        }
#pragma unroll
        for (int i = 0; i < 4; ++i)
#pragma unroll
            for (int j = 0; j < 4; ++j)
                acc2[i][j] = fma2(qf2[i], kf2[j], acc2[i][j]);
    }
#pragma unroll
    for (int i = 0; i < 4; ++i) {
        int ii = (ty << 2) + i;
#pragma unroll
        for (int j = 0; j < 4; ++j) {
            float a0, a1; unpack2(acc2[i][j], a0, a1);
            int jj = (tx << 3) + (j << 1);
            int r0 = rel_idx[(ii << 6) + jj];
            int r1 = rel_idx[(ii << 6) + jj + 1];
            S[ii][jj]     = a0 * scale + rpb[r0 * NHEAD + h];
            S[ii][jj + 1] = a1 * scale + rpb[r1 * NHEAD + h];
        }
    }
#else
    float acc[4][8];
#pragma unroll
    for (int i = 0; i < 4; ++i)
#pragma unroll
        for (int j = 0; j < 8; ++j) acc[i][j] = 0.f;
#pragma unroll 8
    for (int d = 0; d < HDIM; ++d) {
        float qf[4], kf[8];
#pragma unroll
        for (int i = 0; i < 4; ++i) qf[i] = qs[(ty << 2) + i][d];
#pragma unroll
        for (int j = 0; j < 8; ++j) kf[j] = kst[d][(tx << 3) + j];
#pragma unroll
        for (int i = 0; i < 4; ++i)
#pragma unroll
            for (int j = 0; j < 8; ++j)
                acc[i][j] = fmaf(qf[i], kf[j], acc[i][j]);
    }
#pragma unroll
    for (int i = 0; i < 4; ++i) {
        int ii = (ty << 2) + i;
#pragma unroll
        for (int j = 0; j < 8; ++j) {
            int jj = (tx << 3) + j;
            int ridx = rel_idx[(ii << 6) + jj];
            S[ii][jj] = acc[i][j] * scale + rpb[ridx * NHEAD + h];
        }
    }
#endif
    __syncthreads();

    // ---- softmax: 2 threads per row ----
    {
        const int rr = tid >> 1, hf = (tid & 1) << 5;
        float mx = -1e30f;
#pragma unroll 8
        for (int j = 0; j < 32; ++j) mx = fmaxf(mx, S[rr][hf + j]);
        mx = fmaxf(mx, __shfl_xor_sync(0xffffffffu, mx, 1));
        float sum = 0.f;
#pragma unroll 8
        for (int j = 0; j < 32; ++j) {
            float e = __expf(S[rr][hf + j] - mx);
            S[rr][hf + j] = e;
            sum += e;
        }
        sum += __shfl_xor_sync(0xffffffffu, sum, 1);
        float inv = 1.0f / sum;
#pragma unroll 8
        for (int j = 0; j < 32; ++j) S[rr][hf + j] *= inv;
    }
    __syncthreads();

    // ---- O = P @ V ----
    const int dx = tid & 7;
#if HAS_TCGEN05
    uint64_t oacc2[4][2];
#pragma unroll
    for (int i = 0; i < 4; ++i) { oacc2[i][0] = 0ull; oacc2[i][1] = 0ull; }
#pragma unroll 4
    for (int mrow = 0; mrow < 64; ++mrow) {
        uint64_t vf2[2], pf2[4];
        vf2[0] = *(const uint64_t*)&vs[mrow][(dx << 2)];
        vf2[1] = *(const uint64_t*)&vs[mrow][(dx << 2) + 2];
#pragma unroll
        for (int i = 0; i < 4; ++i) {
            float pv = S[(ty << 2) + i][mrow];
            pf2[i] = pack2(pv, pv);
        }
#pragma unroll
        for (int i = 0; i < 4; ++i) {
            oacc2[i][0] = fma2(pf2[i], vf2[0], oacc2[i][0]);
            oacc2[i][1] = fma2(pf2[i], vf2[1], oacc2[i][1]);
        }
    }
#pragma unroll
    for (int i = 0; i < 4; ++i) {
        size_t orow = obase + (size_t)((ty << 2) + i) * CH + (dx << 2);
        float o0, o1, o2, o3;
        unpack2(oacc2[i][0], o0, o1);
        unpack2(oacc2[i][1], o2, o3);
        HF4 H;
        H.h[0] = __float2half_rn(o0); H.h[1] = __float2half_rn(o1);
        H.h[2] = __float2half_rn(o2); H.h[3] = __float2half_rn(o3);
        *(HF4*)(oh + orow) = H;
    }
#else
    float oacc[4][4];
#pragma unroll
    for (int i = 0; i < 4; ++i)
#pragma unroll
        for (int d = 0; d < 4; ++d) oacc[i][d] = 0.f;
#pragma unroll 8
    for (int mrow = 0; mrow < 64; ++mrow) {
        float pf[4], vf[4];
#pragma unroll
        for (int i = 0; i < 4; ++i) pf[i] = S[(ty << 2) + i][mrow];
#pragma unroll
        for (int d = 0; d < 4; ++d) vf[d] = vs[mrow][(dx << 2) + d];
#pragma unroll
        for (int i = 0; i < 4; ++i)
#pragma unroll
            for (int d = 0; d < 4; ++d)
                oacc[i][d] = fmaf(pf[i], vf[d], oacc[i][d]);
    }
#pragma unroll
    for (int i = 0; i < 4; ++i) {
        size_t orow = obase + (size_t)((ty << 2) + i) * CH + (dx << 2);
        HF4 H;
#pragma unroll
        for (int d = 0; d < 4; ++d) H.h[d] = __float2half_rn(oacc[i][d]);
        *(HF4*)(oh + orow) = H;
    }
#endif
}

// ==========================================================================
extern "C" void kernel_launch(void* const* d_in, const int* in_sizes, int n_in,
                              void* d_out, int out_size) {
    const float* x       = (const float*)d_in[0];
    const float* feature = (const float*)d_in[1];
    const float* Wq  = (const float*)d_in[2];
    const float* bq  = (const float*)d_in[3];
    const float* Wk  = (const float*)d_in[4];
    const float* bk  = (const float*)d_in[5];
    const float* Wv  = (const float*)d_in[6];
    const float* bv  = (const float*)d_in[7];
    const float* Wo  = (const float*)d_in[8];
    const float* bo  = (const float*)d_in[9];
    const float* rpb = (const float*)d_in[10];
    const float* g1  = (const float*)d_in[11];
    const float* be1 = (const float*)d_in[12];
    const float* g2  = (const float*)d_in[13];
    const float* be2 = (const float*)d_in[14];
    const float* Wm1 = (const float*)d_in[15];
    const float* bm1 = (const float*)d_in[16];
    const float* Wm2 = (const float*)d_in[17];
    const float* bm2 = (const float*)d_in[18];
    const float* Wu1 = (const float*)d_in[19];
    const float* bu1 = (const float*)d_in[20];
    const float* Wu2 = (const float*)d_in[21];
    const float* bu2 = (const float*)d_in[22];
    const int*   rel = (const int*)d_in[23];
    float* out = (float*)d_out;

    cudaFuncSetAttribute(tgemm<0>, cudaFuncAttributeMaxDynamicSharedMemorySize, TG_SMEM);
    cudaFuncSetAttribute(tgemm<1>, cudaFuncAttributeMaxDynamicSharedMemorySize, TG_SMEM);
    cudaFuncSetAttribute(tgemm<2>, cudaFuncAttributeMaxDynamicSharedMemorySize, TG_SMEM);
    cudaFuncSetAttribute(tgemm<3>, cudaFuncAttributeMaxDynamicSharedMemorySize, TG_SMEM);
    cudaFuncSetAttribute(tgemm<4>, cudaFuncAttributeMaxDynamicSharedMemorySize, TG_SMEM);

    void *p;
    #define SYM(name, var) cudaGetSymbolAddress(&p, name); auto* var = decltype(&name[0])(p)
    SYM(g_qkvh, qkvh);
    SYM(g_unary, unary); SYM(g_x2, x2); SYM(g_bqkv, bqkv);
    SYM(g_xh, xh); SYM(g_th, th); SYM(g_nh, nh);
    SYM(g_oh, oh); SYM(g_lh, lh); SYM(g_hh, hh);
    SYM(g_wthi, wthi); SYM(g_wtlo, wtlo);
    #undef SYM

    // ---- weight transpose + fp16 split; qkv bias concat ----
    wprep_all<<<dim3(32, 32, 8), dim3(32, 8)>>>(Wq, Wk, Wv, Wo, Wu1, Wu2, Wm1, Wm2,
                                                wthi, wtlo);
    biascat<<<1, 768>>>(bq, bk, bv, bqkv);

    // ---- input -> fp16 ----
    cvth<<<(MTOK * CH / 8 + 255) / 256, 256>>>(x, xh, (size_t)MTOK * CH / 8);

    const dim3 g256(2, 1024);     // N=256
    const dim3 g768(6, 1024);     // N=768 (fused qkv)
    const dim3 g1024(8, 1024);    // N=1024

    // unary = gelu(x@Wu1+bu1)@Wu2 + bu2
    tgemm<1><<<g256, 256, TG_SMEM>>>(xh, wthi + WOFF_U1, wtlo + WOFF_U1,
                                     bu1, nullptr, nullptr, th, 256, 256);
    tgemm<0><<<g256, 256, TG_SMEM>>>(th, wthi + WOFF_U2, wtlo + WOFF_U2,
                                     bu2, nullptr, unary, nullptr, 256, 256);

    // feature -> windows + LN1 fused -> fp16
    wln<<<dim3(HWTOK / 32, BATCH), 256>>>(feature, g1, be1, nh);

    // fused q,k,v projection (N=768) -> fp16 qkv
    tgemm<4><<<g768, 256, TG_SMEM>>>(nh, wthi + WOFF_Q, wtlo + WOFF_Q,
                                     bqkv, nullptr, nullptr, qkvh, 256, QKV_STR);

    // attention -> o (fp16)
    attn_kernel<<<NWIN * NHEAD, 128>>>(qkvh, rel, rpb, oh);

    // x2 = unary + scatter(o@Wo + bo)
    tgemm<3><<<g256, 256, TG_SMEM>>>(oh, wthi + WOFF_O, wtlo + WOFF_O,
                                     bo, unary, x2, nullptr, 256, 256);

    // MLP: out = x2 + gelu(LN(x2)@Wm1+bm1)@Wm2 + bm2
    ln256_h<<<MTOK / 8, 256>>>(x2, g2, be2, lh);
    tgemm<1><<<g1024, 256, TG_SMEM>>>(lh, wthi + WOFF_M1, wtlo + WOFF_M1,
                                      bm1, nullptr, nullptr, hh, 256, 1024);
    tgemm<2><<<g256, 256, TG_SMEM>>>(hh, wthi + WOFF_M2, wtlo + WOFF_M2,
                                     bm2, x2, out, nullptr, 1024, 256);
}